// round 17
// baseline (speedup 1.0000x reference)
#include <cuda_runtime.h>
#include <math.h>

#define T_LEN 2048
#define E_DIM 1024
#define D_DIM 1032   // E + H
#define FULLM 0xffffffffu

#define CHUNK 8      // emitted steps per scan warp
#define WARM  20     // warmup steps from zero state
#define NT    16     // timesteps per block (128 blocks)
#define NBLK  (T_LEN / NT)

typedef unsigned long long u64;

// xproj output: float2 per (t, row); .x = k-half 0 (bias folded), .y = half 1.
__device__ float2 g_xp[(T_LEN + 8) * 32];
// Per-block completion flags (zeroed by zero_flags each launch).
__device__ int g_flag[NBLK];

__device__ __forceinline__ float tanhapx(float x) {
    float y;
    asm("tanh.approx.f32 %0, %1;" : "=f"(y) : "f"(x));
    return y;
}
__device__ __forceinline__ int ld_acq(const int* p) {
    int v;
    asm volatile("ld.acquire.gpu.b32 %0, [%1];" : "=r"(v) : "l"(p) : "memory");
    return v;
}
__device__ __forceinline__ void st_rel(int* p, int v) {
    asm volatile("st.release.gpu.b32 [%0], %1;" :: "l"(p), "r"(v) : "memory");
}

#define LDG128(lo, hi, ptr) \
    asm("ld.global.nc.v2.b64 {%0,%1}, [%2];" : "=l"(lo), "=l"(hi) : "l"(ptr))
#define FMA2(acc, a, b) \
    asm("fma.rn.f32x2 %0, %1, %2, %0;" : "+l"(acc) : "l"(a), "l"(b))
#define UNPACK2(lo, hi, p) \
    asm("mov.b64 {%0,%1}, %2;" : "=f"(lo), "=f"(hi) : "l"(p))

// Hillis-Steele segmented (width-8) prefix product, in place.
#define PREFIX8_HS(Z, WW)                                                       \
    {                                                                           \
        float _v;                                                               \
        _v = __shfl_up_sync(FULLM, (Z), 1, 8); if ((WW) >= 1) (Z) *= _v;        \
        _v = __shfl_up_sync(FULLM, (Z), 2, 8); if ((WW) >= 2) (Z) *= _v;        \
        _v = __shfl_up_sync(FULLM, (Z), 4, 8); if ((WW) >= 4) (Z) *= _v;        \
    }

// ---------------------------------------------------------------------------
// Flag reset (graph replays reuse g_flag).
// ---------------------------------------------------------------------------
__global__ void zero_flags()
{
    g_flag[threadIdx.x] = 0;
}

// ---------------------------------------------------------------------------
// Fused kernel: 128 blocks x 576 threads.
//   warps 0..15  : xproj for t in [16b, 16b+16)  (warp = (wire w, k-half kh))
//   warps 16..17 : scan+tag for tEmit = 16b, 16b+8 (CHUNK=8, WARM=20)
// Cross-block deps (scan warm region reads blocks b-2, b-1) via
// release/acquire flags. All 128 blocks are co-resident (1 block/SM), so the
// spin-wait cannot deadlock. Intra-block dep (emit region) via __syncthreads.
// ---------------------------------------------------------------------------
__global__ __launch_bounds__(576, 1)
void fused_kernel(const int* __restrict__ sentence,
                  const float* __restrict__ emb,
                  const float* __restrict__ Wf, const float* __restrict__ bf,
                  const float* __restrict__ Wi, const float* __restrict__ bi,
                  const float* __restrict__ Wu, const float* __restrict__ bu,
                  const float* __restrict__ Wo, const float* __restrict__ bo,
                  const float* __restrict__ rxf, const float* __restrict__ rxi,
                  const float* __restrict__ rxu, const float* __restrict__ rxo,
                  const float* __restrict__ Wtag, const float* __restrict__ btag,
                  float* __restrict__ out)
{
    const int b    = blockIdx.x;
    const int tid  = threadIdx.x;
    const int lane = tid & 31;

    __shared__ float sWtagT[64], sbtag[8], sh_h[2][CHUNK][8];

    // Scan-warp per-thread state computed in prologue (kept in regs).
    float Wh[8], K = 0.f, postMul = 0.f, postAdd = 0.f;

    if (tid < 512) {
        // ----------------- xproj: 16 warps, warp = (w, kh) ------------------
        const int warp = tid >> 5;
        const int w    = warp >> 1;
        const int kh   = warp & 1;

        const float* r0 = Wf + (size_t)w * D_DIM;
        const float* r1 = Wi + (size_t)w * D_DIM;
        const float* r2 = Wu + (size_t)w * D_DIM;
        const float* r3 = Wo + (size_t)w * D_DIM;

        u64 W0[4][2], W1[4][2], W2[4][2], W3[4][2];
        #pragma unroll
        for (int kc = 0; kc < 4; ++kc) {
            const int off = kh * 512 + 4 * (lane + 32 * kc);
            LDG128(W0[kc][0], W0[kc][1], r0 + off);
            LDG128(W1[kc][0], W1[kc][1], r1 + off);
            LDG128(W2[kc][0], W2[kc][1], r2 + off);
            LDG128(W3[kc][0], W3[kc][1], r3 + off);
        }
        const float bsel = kh ? 0.f : 1.f;
        const float b0 = bf[w] * bsel, b1 = bi[w] * bsel,
                    b2 = bu[w] * bsel, b3 = bo[w] * bsel;

        float* dstBase = ((float*)g_xp) + kh;
        const int t0 = b * NT;

        #pragma unroll 2
        for (int tt = 0; tt < NT; ++tt) {
            const int idx = __ldg(sentence + t0 + tt);
            const float* xr = emb + (size_t)idx * E_DIM + kh * 512;

            u64 a0 = 0, a1 = 0, a2 = 0, a3 = 0;
            #pragma unroll
            for (int kc = 0; kc < 4; ++kc) {
                u64 x0, x1;
                LDG128(x0, x1, xr + 4 * (lane + 32 * kc));
                FMA2(a0, x0, W0[kc][0]);  FMA2(a0, x1, W0[kc][1]);
                FMA2(a1, x0, W1[kc][0]);  FMA2(a1, x1, W1[kc][1]);
                FMA2(a2, x0, W2[kc][0]);  FMA2(a2, x1, W2[kc][1]);
                FMA2(a3, x0, W3[kc][0]);  FMA2(a3, x1, W3[kc][1]);
            }
            float s0, s1, s2, s3, lo, hi;
            UNPACK2(lo, hi, a0); s0 = lo + hi;
            UNPACK2(lo, hi, a1); s1 = lo + hi;
            UNPACK2(lo, hi, a2); s2 = lo + hi;
            UNPACK2(lo, hi, a3); s3 = lo + hi;
            #pragma unroll
            for (int d = 16; d; d >>= 1) {
                s0 += __shfl_xor_sync(FULLM, s0, d);
                s1 += __shfl_xor_sync(FULLM, s1, d);
                s2 += __shfl_xor_sync(FULLM, s2, d);
                s3 += __shfl_xor_sync(FULLM, s3, d);
            }
            if (lane == 0) {
                float* dst = dstBase + 2 * ((t0 + tt) * 32 + w);
                dst[0]  = s0 + b0;
                dst[16] = s1 + b1;
                dst[32] = s2 + b2;
                dst[48] = s3 + b3;
            }
        }
        __threadfence();   // order g_xp stores before the release flag
    } else {
        // ----------------- scan prologue (overlaps xproj) -------------------
        const int g = lane >> 3;
        const int w = lane & 7;
        const float* Wg  = (g == 0) ? Wf  : (g == 1) ? Wi  : (g == 2) ? Wu  : Wo;
        const float* rxg = (g == 0) ? rxf : (g == 1) ? rxi : (g == 2) ? rxu : rxo;

        const float4* p = (const float4*)(Wg + (size_t)w * D_DIM + E_DIM);
        const float4 v0 = __ldg(p), v1 = __ldg(p + 1);
        Wh[0] = v0.x; Wh[1] = v0.y; Wh[2] = v0.z; Wh[3] = v0.w;
        Wh[4] = v1.x; Wh[5] = v1.y; Wh[6] = v1.z; Wh[7] = v1.w;

        K = __cosf(__ldg(rxg + w));
        PREFIX8_HS(K, w);
        postMul = (g == 2) ? 1.f : 0.5f;
        postAdd = (g == 2) ? 0.f : 0.5f;
        K *= (g == 2) ? 1.f : 0.5f;

        if (tid < 544) {   // warp 16 stages tag weights
            const int e0 = lane, e1 = lane + 32;
            sWtagT[(e0 & 7) * 8 + (e0 >> 3)] = __ldg(Wtag + e0);
            sWtagT[(e1 & 7) * 8 + (e1 >> 3)] = __ldg(Wtag + e1);
            if (lane < 8) sbtag[lane] = __ldg(btag + lane);
        }
    }

    __syncthreads();

    if (tid < 512) {
        if (tid == 0) st_rel(&g_flag[b], 1);   // publish this block's g_xp
        return;
    }

    // --------------------------- scan + tag --------------------------------
    const int sw = (tid - 512) >> 5;          // 0 or 1
    const int g  = lane >> 3;
    const int w  = lane & 7;

    const int tEmit  = b * NT + sw * CHUNK;
    const int tStart = (tEmit > WARM) ? (tEmit - WARM) : 0;

    // Wait for the other blocks this warp reads (all loads are < tEmit+8).
    {
        const int jmin = tStart >> 4;
        const int jmax = (tEmit + CHUNK - 1) >> 4;
        for (int j = jmin; j <= jmax; ++j)
            if (j != b)
                while (ld_acq(&g_flag[j]) == 0) {}
    }

    float hw = 0.f, cw = 0.f;

    float2 xp0 = g_xp[(tStart + 0) * 32 + lane];
    float2 xp1 = g_xp[(tStart + 1) * 32 + lane];
    float2 xp2 = g_xp[(tStart + 2) * 32 + lane];
    float2 xp3 = g_xp[(tStart + 3) * 32 + lane];

#define QLSTM_STEP(XP, PRED, KIDX)                                              \
    {                                                                           \
        const float h0 = __shfl_sync(FULLM, hw, 0, 8);                          \
        const float h1 = __shfl_sync(FULLM, hw, 1, 8);                          \
        const float h2 = __shfl_sync(FULLM, hw, 2, 8);                          \
        const float h3 = __shfl_sync(FULLM, hw, 3, 8);                          \
        const float h4 = __shfl_sync(FULLM, hw, 4, 8);                          \
        const float h5 = __shfl_sync(FULLM, hw, 5, 8);                          \
        const float h6 = __shfl_sync(FULLM, hw, 6, 8);                          \
        const float h7 = __shfl_sync(FULLM, hw, 7, 8);                          \
        const float s0 = fmaf(h0, Wh[0], h1 * Wh[1]);                           \
        const float s1 = fmaf(h2, Wh[2], h3 * Wh[3]);                           \
        const float s2 = fmaf(h4, Wh[4], h5 * Wh[5]);                           \
        const float s3 = fmaf(h6, Wh[6], h7 * Wh[7]);                           \
        const float a  = (((XP).x + (XP).y) + (s0 + s1)) + (s2 + s3);           \
        float pc = __cosf(a);                                                   \
        PREFIX8_HS(pc, w);                                                      \
        const float act = fmaf(tanhapx(pc * K), postMul, postAdd);              \
        const float f = __shfl_sync(FULLM, act, w,      32);                    \
        const float i = __shfl_sync(FULLM, act, 8 + w,  32);                    \
        const float u = __shfl_sync(FULLM, act, 16 + w, 32);                    \
        const float o = __shfl_sync(FULLM, act, 24 + w, 32);                    \
        cw = fmaf(f, cw, i * u);                                                \
        hw = o * tanhapx(cw);                                                   \
        if ((PRED) && g == 0) sh_h[sw][KIDX][w] = hw;                           \
    }

    if (tStart > 0) {
        // Warmup: WARM steps, no stores. All loads stay < tEmit+8.
        for (int t = tStart; t < tEmit; t += 4) {
            QLSTM_STEP(xp0, false, 0); xp0 = g_xp[(t + 4) * 32 + lane];
            QLSTM_STEP(xp1, false, 0); xp1 = g_xp[(t + 5) * 32 + lane];
            QLSTM_STEP(xp2, false, 0); xp2 = g_xp[(t + 6) * 32 + lane];
            QLSTM_STEP(xp3, false, 0); xp3 = g_xp[(t + 7) * 32 + lane];
        }
        // Emit CHUNK=8 (loads up to tEmit+7 only).
        QLSTM_STEP(xp0, true, 0); xp0 = g_xp[(tEmit + 4) * 32 + lane];
        QLSTM_STEP(xp1, true, 1); xp1 = g_xp[(tEmit + 5) * 32 + lane];
        QLSTM_STEP(xp2, true, 2); xp2 = g_xp[(tEmit + 6) * 32 + lane];
        QLSTM_STEP(xp3, true, 3); xp3 = g_xp[(tEmit + 7) * 32 + lane];
        QLSTM_STEP(xp0, true, 4);
        QLSTM_STEP(xp1, true, 5);
        QLSTM_STEP(xp2, true, 6);
        QLSTM_STEP(xp3, true, 7);
    } else {
        // Exact path from t=0 (tEmit <= 20; at most 28 steps, loads < tEmit+8).
        const int tEnd = tEmit + CHUNK;
        for (int t = 0; t < tEnd; t += 4) {
            QLSTM_STEP(xp0, (t + 0) >= tEmit, (t + 0) - tEmit);
            if (t + 4 < tEnd) xp0 = g_xp[(t + 4) * 32 + lane];
            QLSTM_STEP(xp1, (t + 1) >= tEmit, (t + 1) - tEmit);
            if (t + 5 < tEnd) xp1 = g_xp[(t + 5) * 32 + lane];
            QLSTM_STEP(xp2, (t + 2) >= tEmit, (t + 2) - tEmit);
            if (t + 6 < tEnd) xp2 = g_xp[(t + 6) * 32 + lane];
            QLSTM_STEP(xp3, (t + 3) >= tEmit, (t + 3) - tEmit);
            if (t + 7 < tEnd) xp3 = g_xp[(t + 7) * 32 + lane];
        }
    }
#undef QLSTM_STEP

    __syncwarp();

    // Fused tag head: lane = tl*8 + ww; two passes cover this warp's 8 steps.
    {
        const int tl = lane >> 3;
        const int ww = w;
        #pragma unroll
        for (int rep = 0; rep < 2; ++rep) {
            const int row = rep * 4 + tl;
            float a = sbtag[ww];
            #pragma unroll
            for (int j = 0; j < 8; ++j)
                a = fmaf(sh_h[sw][row][j], sWtagT[j * 8 + ww], a);
            float z = __cosf(a);
            PREFIX8_HS(z, ww);
            out[(tEmit + row) * 8 + ww] = __logf(fmaf(z, 0.5f, 0.5f) + 1e-12f);
        }
    }
}

// ---------------------------------------------------------------------------
extern "C" void kernel_launch(void* const* d_in, const int* in_sizes, int n_in,
                              void* d_out, int out_size)
{
    const int*   sentence = (const int*)  d_in[0];
    const float* emb      = (const float*)d_in[1];
    const float* Wf       = (const float*)d_in[2];
    const float* bf       = (const float*)d_in[3];
    const float* Wi       = (const float*)d_in[4];
    const float* bi       = (const float*)d_in[5];
    const float* Wu       = (const float*)d_in[6];
    const float* bu       = (const float*)d_in[7];
    const float* Wo       = (const float*)d_in[8];
    const float* bo       = (const float*)d_in[9];
    const float* rxf      = (const float*)d_in[10];
    const float* rxi      = (const float*)d_in[11];
    const float* rxu      = (const float*)d_in[12];
    const float* rxo      = (const float*)d_in[13];
    const float* Wtag     = (const float*)d_in[14];
    const float* btag     = (const float*)d_in[15];

    zero_flags<<<1, NBLK>>>();
    fused_kernel<<<NBLK, 576>>>(sentence, emb, Wf, bf, Wi, bi, Wu, bu, Wo, bo,
                                rxf, rxi, rxu, rxo, Wtag, btag, (float*)d_out);
}